// round 2
// baseline (speedup 1.0000x reference)
#include <cuda_runtime.h>
#include <math.h>

// Problem constants
#define T_TOKENS 16384   // B*L = 4*4096
#define DDIM     1024
#define NEXP     8
#define TM 64
#define TN 64
#define TK 16

// ---------------- scratch (static device globals; no allocation) ------------
__device__ int   g_count[NEXP];                 // tokens routed to each expert
__device__ int   g_base[NEXP];                  // exclusive prefix of counts
__device__ int   g_tok[NEXP][T_TOKENS];         // token index per slot
__device__ float g_w  [NEXP][T_TOKENS];         // routing weight per slot
__device__ float g_H  [2 * T_TOKENS * DDIM];    // packed hidden activations (128 MB)

// ---------------- init ------------------------------------------------------
__global__ void init_counts_kernel() {
    if (threadIdx.x < NEXP) g_count[threadIdx.x] = 0;
}

// ---------------- router: logits -> top2 -> renormalized weights ------------
// one warp per token, 8 tokens per block
__global__ void router_kernel(const float* __restrict__ x,
                              const float* __restrict__ Wr) {
    __shared__ __align__(16) float sWr[NEXP * DDIM];   // 32 KB
    for (int i = threadIdx.x; i < NEXP * DDIM; i += blockDim.x) sWr[i] = Wr[i];
    __syncthreads();

    const int warp = threadIdx.x >> 5;
    const int lane = threadIdx.x & 31;
    const int t = blockIdx.x * 8 + warp;            // token id, grid covers exactly T

    const float4* xr = (const float4*)(x + (size_t)t * DDIM);
    const float4* wr = (const float4*)sWr;

    float acc[NEXP];
#pragma unroll
    for (int e = 0; e < NEXP; e++) acc[e] = 0.f;

    for (int i = lane; i < DDIM / 4; i += 32) {
        float4 xv = xr[i];
#pragma unroll
        for (int e = 0; e < NEXP; e++) {
            float4 wv = wr[e * (DDIM / 4) + i];
            acc[e] += xv.x * wv.x + xv.y * wv.y + xv.z * wv.z + xv.w * wv.w;
        }
    }
#pragma unroll
    for (int e = 0; e < NEXP; e++)
#pragma unroll
        for (int off = 16; off; off >>= 1)
            acc[e] += __shfl_xor_sync(0xffffffffu, acc[e], off);

    if (lane == 0) {
        // top-1
        int i1 = 0; float m1 = acc[0];
#pragma unroll
        for (int e = 1; e < NEXP; e++)
            if (acc[e] > m1) { m1 = acc[e]; i1 = e; }
        // top-2 (lowest index wins ties, matching top_k)
        int i2 = -1; float m2 = -INFINITY;
#pragma unroll
        for (int e = 0; e < NEXP; e++)
            if (e != i1 && acc[e] > m2) { m2 = acc[e]; i2 = e; }

        // softmax over {m1,m2} == softmax over all, renormalized to top-2
        float w1 = 1.0f / (1.0f + expf(m2 - m1));
        float w2 = 1.0f - w1;

        int p1 = atomicAdd(&g_count[i1], 1);
        g_tok[i1][p1] = t; g_w[i1][p1] = w1;
        int p2 = atomicAdd(&g_count[i2], 1);
        g_tok[i2][p2] = t; g_w[i2][p2] = w2;
    }
}

__global__ void prefix_kernel() {
    if (threadIdx.x == 0) {
        int s = 0;
#pragma unroll
        for (int e = 0; e < NEXP; e++) { g_base[e] = s; s += g_count[e]; }
    }
}

// ---------------- GEMM1: H = gelu(Xg @ W1[e]^T + b1[e]) ---------------------
// A: gathered token rows of x   [cnt, D]
// B: W1[e]  (row f, col d) row-major  -> C[m, f] = sum_d A[m,d] * W1[f,d]
__global__ void __launch_bounds__(256)
gemm1_kernel(const float* __restrict__ x,
             const float* __restrict__ W1,
             const float* __restrict__ b1) {
    const int e    = blockIdx.z;
    const int cnt  = g_count[e];
    const int row0 = blockIdx.y * TM;
    if (row0 >= cnt) return;
    const int col0 = blockIdx.x * TN;
    const int base = g_base[e];

    __shared__ __align__(16) float As[TK][TM + 4];
    __shared__ __align__(16) float Bs[TK][TN + 4];
    __shared__ int sTok[TM];

    const int tid = threadIdx.x;
    if (tid < TM) {
        int r = row0 + tid;
        sTok[tid] = g_tok[e][min(r, cnt - 1)];
    }
    __syncthreads();

    const int tx = tid & 15, ty = tid >> 4;
    const int lrow = tid >> 2;           // 0..63
    const int lk4  = (tid & 3) * 4;      // 0,4,8,12

    const size_t arow  = (size_t)sTok[lrow] * DDIM;
    const float* Bbase = W1 + ((size_t)e * DDIM + (col0 + lrow)) * DDIM;

    float c[4][4];
#pragma unroll
    for (int i = 0; i < 4; i++)
#pragma unroll
        for (int j = 0; j < 4; j++) c[i][j] = 0.f;

    for (int k0 = 0; k0 < DDIM; k0 += TK) {
        float4 av = *(const float4*)(x + arow + k0 + lk4);
        float4 bv = *(const float4*)(Bbase + k0 + lk4);
        __syncthreads();
        As[lk4 + 0][lrow] = av.x; As[lk4 + 1][lrow] = av.y;
        As[lk4 + 2][lrow] = av.z; As[lk4 + 3][lrow] = av.w;
        Bs[lk4 + 0][lrow] = bv.x; Bs[lk4 + 1][lrow] = bv.y;
        Bs[lk4 + 2][lrow] = bv.z; Bs[lk4 + 3][lrow] = bv.w;
        __syncthreads();
#pragma unroll
        for (int k = 0; k < TK; k++) {
            float4 a = *(const float4*)&As[k][ty * 4];
            float4 b = *(const float4*)&Bs[k][tx * 4];
            c[0][0] += a.x * b.x; c[0][1] += a.x * b.y; c[0][2] += a.x * b.z; c[0][3] += a.x * b.w;
            c[1][0] += a.y * b.x; c[1][1] += a.y * b.y; c[1][2] += a.y * b.z; c[1][3] += a.y * b.w;
            c[2][0] += a.z * b.x; c[2][1] += a.z * b.y; c[2][2] += a.z * b.z; c[2][3] += a.z * b.w;
            c[3][0] += a.w * b.x; c[3][1] += a.w * b.y; c[3][2] += a.w * b.z; c[3][3] += a.w * b.w;
        }
    }

#pragma unroll
    for (int i = 0; i < 4; i++) {
        int r = row0 + ty * 4 + i;
        if (r < cnt) {
            float* hrow = g_H + (size_t)(base + r) * DDIM;
#pragma unroll
            for (int j = 0; j < 4; j++) {
                int f = col0 + tx * 4 + j;
                float v = c[i][j] + b1[e * DDIM + f];
                // exact gelu: 0.5*v*(1+erf(v/sqrt(2)))
                hrow[f] = 0.5f * v * (1.0f + erff(v * 0.70710678118654752f));
            }
        }
    }
}

// ---------------- GEMM2: out[tok] += w * (H @ W2[e]^T + b2[e]) ---------------
// A: packed H rows [cnt, D];  B: W2[e] (row d, col f) -> C[m, d] = sum_f H[m,f]*W2[d,f]
__global__ void __launch_bounds__(256)
gemm2_kernel(const float* __restrict__ W2,
             const float* __restrict__ b2,
             float* __restrict__ out) {
    const int e    = blockIdx.z;
    const int cnt  = g_count[e];
    const int row0 = blockIdx.y * TM;
    if (row0 >= cnt) return;
    const int col0 = blockIdx.x * TN;
    const int base = g_base[e];

    __shared__ __align__(16) float As[TK][TM + 4];
    __shared__ __align__(16) float Bs[TK][TN + 4];

    const int tid = threadIdx.x;
    const int tx = tid & 15, ty = tid >> 4;
    const int lrow = tid >> 2;
    const int lk4  = (tid & 3) * 4;

    const int rA = min(row0 + lrow, cnt - 1);
    const float* Abase = g_H + (size_t)(base + rA) * DDIM;
    const float* Bbase = W2 + ((size_t)e * DDIM + (col0 + lrow)) * DDIM;

    float c[4][4];
#pragma unroll
    for (int i = 0; i < 4; i++)
#pragma unroll
        for (int j = 0; j < 4; j++) c[i][j] = 0.f;

    for (int k0 = 0; k0 < DDIM; k0 += TK) {
        float4 av = *(const float4*)(Abase + k0 + lk4);
        float4 bv = *(const float4*)(Bbase + k0 + lk4);
        __syncthreads();
        As[lk4 + 0][lrow] = av.x; As[lk4 + 1][lrow] = av.y;
        As[lk4 + 2][lrow] = av.z; As[lk4 + 3][lrow] = av.w;
        Bs[lk4 + 0][lrow] = bv.x; Bs[lk4 + 1][lrow] = bv.y;
        Bs[lk4 + 2][lrow] = bv.z; Bs[lk4 + 3][lrow] = bv.w;
        __syncthreads();
#pragma unroll
        for (int k = 0; k < TK; k++) {
            float4 a = *(const float4*)&As[k][ty * 4];
            float4 b = *(const float4*)&Bs[k][tx * 4];
            c[0][0] += a.x * b.x; c[0][1] += a.x * b.y; c[0][2] += a.x * b.z; c[0][3] += a.x * b.w;
            c[1][0] += a.y * b.x; c[1][1] += a.y * b.y; c[1][2] += a.y * b.z; c[1][3] += a.y * b.w;
            c[2][0] += a.z * b.x; c[2][1] += a.z * b.y; c[2][2] += a.z * b.z; c[2][3] += a.z * b.w;
            c[3][0] += a.w * b.x; c[3][1] += a.w * b.y; c[3][2] += a.w * b.z; c[3][3] += a.w * b.w;
        }
    }

#pragma unroll
    for (int i = 0; i < 4; i++) {
        int r = row0 + ty * 4 + i;
        if (r < cnt) {
            int   tok = g_tok[e][r];
            float w   = g_w[e][r];
            float* orow = out + (size_t)tok * DDIM;
#pragma unroll
            for (int j = 0; j < 4; j++) {
                int dcol = col0 + tx * 4 + j;
                float y = c[i][j] + b2[e * DDIM + dcol];
                atomicAdd(&orow[dcol], w * y);
            }
        }
    }
}

// ---------------- launch -----------------------------------------------------
extern "C" void kernel_launch(void* const* d_in, const int* in_sizes, int n_in,
                              void* d_out, int out_size) {
    const float* x  = (const float*)d_in[0];
    const float* Wr = (const float*)d_in[1];
    const float* W1 = (const float*)d_in[2];
    const float* b1 = (const float*)d_in[3];
    const float* W2 = (const float*)d_in[4];
    const float* b2 = (const float*)d_in[5];
    float* out = (float*)d_out;

    init_counts_kernel<<<1, 32>>>();
    router_kernel<<<T_TOKENS / 8, 256>>>(x, Wr);
    prefix_kernel<<<1, 32>>>();
    cudaMemsetAsync(d_out, 0, (size_t)out_size * sizeof(float), 0);

    dim3 grid(DDIM / TN, T_TOKENS / TM, NEXP);   // (16, 256, 8), early-exit on count
    gemm1_kernel<<<grid, 256>>>(x, W1, b1);
    gemm2_kernel<<<grid, 256>>>(W2, b2, out);
}

// round 3
// speedup vs baseline: 1.0013x; 1.0013x over previous
#include <cuda_runtime.h>
#include <math.h>

// Problem constants
#define T_TOKENS 16384   // B*L = 4*4096
#define DDIM     1024
#define NEXP     8
#define TM 64
#define TN 64
#define TK 16

// ---------------- scratch (static device globals; no allocation) ------------
__device__ int   g_count[NEXP];                 // tokens routed to each expert
__device__ int   g_base[NEXP];                  // exclusive prefix of counts
__device__ int   g_tok[NEXP][T_TOKENS];         // token index per slot
__device__ float g_w  [NEXP][T_TOKENS];         // routing weight per slot
__device__ float g_H  [2 * T_TOKENS * DDIM];    // packed hidden activations (128 MB)

// ---------------- init ------------------------------------------------------
__global__ void init_counts_kernel() {
    if (threadIdx.x < NEXP) g_count[threadIdx.x] = 0;
}

// ---------------- router: logits -> top2 -> renormalized weights ------------
// one warp per token, 8 tokens per block
__global__ void router_kernel(const float* __restrict__ x,
                              const float* __restrict__ Wr) {
    __shared__ __align__(16) float sWr[NEXP * DDIM];   // 32 KB
    for (int i = threadIdx.x; i < NEXP * DDIM; i += blockDim.x) sWr[i] = Wr[i];
    __syncthreads();

    const int warp = threadIdx.x >> 5;
    const int lane = threadIdx.x & 31;
    const int t = blockIdx.x * 8 + warp;            // token id, grid covers exactly T

    const float4* xr = (const float4*)(x + (size_t)t * DDIM);
    const float4* wr = (const float4*)sWr;

    float acc[NEXP];
#pragma unroll
    for (int e = 0; e < NEXP; e++) acc[e] = 0.f;

    for (int i = lane; i < DDIM / 4; i += 32) {
        float4 xv = xr[i];
#pragma unroll
        for (int e = 0; e < NEXP; e++) {
            float4 wv = wr[e * (DDIM / 4) + i];
            acc[e] += xv.x * wv.x + xv.y * wv.y + xv.z * wv.z + xv.w * wv.w;
        }
    }
#pragma unroll
    for (int e = 0; e < NEXP; e++)
#pragma unroll
        for (int off = 16; off; off >>= 1)
            acc[e] += __shfl_xor_sync(0xffffffffu, acc[e], off);

    if (lane == 0) {
        // top-1
        int i1 = 0; float m1 = acc[0];
#pragma unroll
        for (int e = 1; e < NEXP; e++)
            if (acc[e] > m1) { m1 = acc[e]; i1 = e; }
        // top-2 (lowest index wins ties, matching top_k)
        int i2 = -1; float m2 = -INFINITY;
#pragma unroll
        for (int e = 0; e < NEXP; e++)
            if (e != i1 && acc[e] > m2) { m2 = acc[e]; i2 = e; }

        // softmax over {m1,m2} == softmax over all, renormalized to top-2
        float w1 = 1.0f / (1.0f + expf(m2 - m1));
        float w2 = 1.0f - w1;

        int p1 = atomicAdd(&g_count[i1], 1);
        g_tok[i1][p1] = t; g_w[i1][p1] = w1;
        int p2 = atomicAdd(&g_count[i2], 1);
        g_tok[i2][p2] = t; g_w[i2][p2] = w2;
    }
}

__global__ void prefix_kernel() {
    if (threadIdx.x == 0) {
        int s = 0;
#pragma unroll
        for (int e = 0; e < NEXP; e++) { g_base[e] = s; s += g_count[e]; }
    }
}

// ---------------- GEMM1: H = gelu(Xg @ W1[e]^T + b1[e]) ---------------------
// A: gathered token rows of x   [cnt, D]
// B: W1[e]  (row f, col d) row-major  -> C[m, f] = sum_d A[m,d] * W1[f,d]
__global__ void __launch_bounds__(256)
gemm1_kernel(const float* __restrict__ x,
             const float* __restrict__ W1,
             const float* __restrict__ b1) {
    const int e    = blockIdx.z;
    const int cnt  = g_count[e];
    const int row0 = blockIdx.y * TM;
    if (row0 >= cnt) return;
    const int col0 = blockIdx.x * TN;
    const int base = g_base[e];

    __shared__ __align__(16) float As[TK][TM + 4];
    __shared__ __align__(16) float Bs[TK][TN + 4];
    __shared__ int sTok[TM];

    const int tid = threadIdx.x;
    if (tid < TM) {
        int r = row0 + tid;
        sTok[tid] = g_tok[e][min(r, cnt - 1)];
    }
    __syncthreads();

    const int tx = tid & 15, ty = tid >> 4;
    const int lrow = tid >> 2;           // 0..63
    const int lk4  = (tid & 3) * 4;      // 0,4,8,12

    const size_t arow  = (size_t)sTok[lrow] * DDIM;
    const float* Bbase = W1 + ((size_t)e * DDIM + (col0 + lrow)) * DDIM;

    float c[4][4];
#pragma unroll
    for (int i = 0; i < 4; i++)
#pragma unroll
        for (int j = 0; j < 4; j++) c[i][j] = 0.f;

    for (int k0 = 0; k0 < DDIM; k0 += TK) {
        float4 av = *(const float4*)(x + arow + k0 + lk4);
        float4 bv = *(const float4*)(Bbase + k0 + lk4);
        __syncthreads();
        As[lk4 + 0][lrow] = av.x; As[lk4 + 1][lrow] = av.y;
        As[lk4 + 2][lrow] = av.z; As[lk4 + 3][lrow] = av.w;
        Bs[lk4 + 0][lrow] = bv.x; Bs[lk4 + 1][lrow] = bv.y;
        Bs[lk4 + 2][lrow] = bv.z; Bs[lk4 + 3][lrow] = bv.w;
        __syncthreads();
#pragma unroll
        for (int k = 0; k < TK; k++) {
            float4 a = *(const float4*)&As[k][ty * 4];
            float4 b = *(const float4*)&Bs[k][tx * 4];
            c[0][0] += a.x * b.x; c[0][1] += a.x * b.y; c[0][2] += a.x * b.z; c[0][3] += a.x * b.w;
            c[1][0] += a.y * b.x; c[1][1] += a.y * b.y; c[1][2] += a.y * b.z; c[1][3] += a.y * b.w;
            c[2][0] += a.z * b.x; c[2][1] += a.z * b.y; c[2][2] += a.z * b.z; c[2][3] += a.z * b.w;
            c[3][0] += a.w * b.x; c[3][1] += a.w * b.y; c[3][2] += a.w * b.z; c[3][3] += a.w * b.w;
        }
    }

#pragma unroll
    for (int i = 0; i < 4; i++) {
        int r = row0 + ty * 4 + i;
        if (r < cnt) {
            float* hrow = g_H + (size_t)(base + r) * DDIM;
#pragma unroll
            for (int j = 0; j < 4; j++) {
                int f = col0 + tx * 4 + j;
                float v = c[i][j] + b1[e * DDIM + f];
                // exact gelu: 0.5*v*(1+erf(v/sqrt(2)))
                hrow[f] = 0.5f * v * (1.0f + erff(v * 0.70710678118654752f));
            }
        }
    }
}

// ---------------- GEMM2: out[tok] += w * (H @ W2[e]^T + b2[e]) ---------------
// A: packed H rows [cnt, D];  B: W2[e] (row d, col f) -> C[m, d] = sum_f H[m,f]*W2[d,f]
__global__ void __launch_bounds__(256)
gemm2_kernel(const float* __restrict__ W2,
             const float* __restrict__ b2,
             float* __restrict__ out) {
    const int e    = blockIdx.z;
    const int cnt  = g_count[e];
    const int row0 = blockIdx.y * TM;
    if (row0 >= cnt) return;
    const int col0 = blockIdx.x * TN;
    const int base = g_base[e];

    __shared__ __align__(16) float As[TK][TM + 4];
    __shared__ __align__(16) float Bs[TK][TN + 4];

    const int tid = threadIdx.x;
    const int tx = tid & 15, ty = tid >> 4;
    const int lrow = tid >> 2;
    const int lk4  = (tid & 3) * 4;

    const int rA = min(row0 + lrow, cnt - 1);
    const float* Abase = g_H + (size_t)(base + rA) * DDIM;
    const float* Bbase = W2 + ((size_t)e * DDIM + (col0 + lrow)) * DDIM;

    float c[4][4];
#pragma unroll
    for (int i = 0; i < 4; i++)
#pragma unroll
        for (int j = 0; j < 4; j++) c[i][j] = 0.f;

    for (int k0 = 0; k0 < DDIM; k0 += TK) {
        float4 av = *(const float4*)(Abase + k0 + lk4);
        float4 bv = *(const float4*)(Bbase + k0 + lk4);
        __syncthreads();
        As[lk4 + 0][lrow] = av.x; As[lk4 + 1][lrow] = av.y;
        As[lk4 + 2][lrow] = av.z; As[lk4 + 3][lrow] = av.w;
        Bs[lk4 + 0][lrow] = bv.x; Bs[lk4 + 1][lrow] = bv.y;
        Bs[lk4 + 2][lrow] = bv.z; Bs[lk4 + 3][lrow] = bv.w;
        __syncthreads();
#pragma unroll
        for (int k = 0; k < TK; k++) {
            float4 a = *(const float4*)&As[k][ty * 4];
            float4 b = *(const float4*)&Bs[k][tx * 4];
            c[0][0] += a.x * b.x; c[0][1] += a.x * b.y; c[0][2] += a.x * b.z; c[0][3] += a.x * b.w;
            c[1][0] += a.y * b.x; c[1][1] += a.y * b.y; c[1][2] += a.y * b.z; c[1][3] += a.y * b.w;
            c[2][0] += a.z * b.x; c[2][1] += a.z * b.y; c[2][2] += a.z * b.z; c[2][3] += a.z * b.w;
            c[3][0] += a.w * b.x; c[3][1] += a.w * b.y; c[3][2] += a.w * b.z; c[3][3] += a.w * b.w;
        }
    }

#pragma unroll
    for (int i = 0; i < 4; i++) {
        int r = row0 + ty * 4 + i;
        if (r < cnt) {
            int   tok = g_tok[e][r];
            float w   = g_w[e][r];
            float* orow = out + (size_t)tok * DDIM;
#pragma unroll
            for (int j = 0; j < 4; j++) {
                int dcol = col0 + tx * 4 + j;
                float y = c[i][j] + b2[e * DDIM + dcol];
                atomicAdd(&orow[dcol], w * y);
            }
        }
    }
}

// ---------------- launch -----------------------------------------------------
extern "C" void kernel_launch(void* const* d_in, const int* in_sizes, int n_in,
                              void* d_out, int out_size) {
    const float* x  = (const float*)d_in[0];
    const float* Wr = (const float*)d_in[1];
    const float* W1 = (const float*)d_in[2];
    const float* b1 = (const float*)d_in[3];
    const float* W2 = (const float*)d_in[4];
    const float* b2 = (const float*)d_in[5];
    float* out = (float*)d_out;

    init_counts_kernel<<<1, 32>>>();
    router_kernel<<<T_TOKENS / 8, 256>>>(x, Wr);
    prefix_kernel<<<1, 32>>>();
    cudaMemsetAsync(d_out, 0, (size_t)out_size * sizeof(float), 0);

    dim3 grid(DDIM / TN, T_TOKENS / TM, NEXP);   // (16, 256, 8), early-exit on count
    gemm1_kernel<<<grid, 256>>>(x, W1, b1);
    gemm2_kernel<<<grid, 256>>>(W2, b2, out);
}

// round 4
// speedup vs baseline: 1.0013x; 1.0000x over previous
#include <cuda_runtime.h>
#include <math.h>

// Problem constants
#define T_TOKENS 16384   // B*L = 4*4096
#define DDIM     1024
#define NEXP     8
#define TM 64
#define TN 64
#define TK 16

// ---------------- scratch (static device globals; no allocation) ------------
__device__ int   g_count[NEXP];                 // tokens routed to each expert
__device__ int   g_base[NEXP];                  // exclusive prefix of counts
__device__ int   g_tok[NEXP][T_TOKENS];         // token index per slot
__device__ float g_w  [NEXP][T_TOKENS];         // routing weight per slot
__device__ float g_H  [2 * T_TOKENS * DDIM];    // packed hidden activations (128 MB)

// ---------------- init ------------------------------------------------------
__global__ void init_counts_kernel() {
    if (threadIdx.x < NEXP) g_count[threadIdx.x] = 0;
}

// ---------------- router: logits -> top2 -> renormalized weights ------------
// one warp per token, 8 tokens per block
__global__ void router_kernel(const float* __restrict__ x,
                              const float* __restrict__ Wr) {
    __shared__ __align__(16) float sWr[NEXP * DDIM];   // 32 KB
    for (int i = threadIdx.x; i < NEXP * DDIM; i += blockDim.x) sWr[i] = Wr[i];
    __syncthreads();

    const int warp = threadIdx.x >> 5;
    const int lane = threadIdx.x & 31;
    const int t = blockIdx.x * 8 + warp;            // token id, grid covers exactly T

    const float4* xr = (const float4*)(x + (size_t)t * DDIM);
    const float4* wr = (const float4*)sWr;

    float acc[NEXP];
#pragma unroll
    for (int e = 0; e < NEXP; e++) acc[e] = 0.f;

    for (int i = lane; i < DDIM / 4; i += 32) {
        float4 xv = xr[i];
#pragma unroll
        for (int e = 0; e < NEXP; e++) {
            float4 wv = wr[e * (DDIM / 4) + i];
            acc[e] += xv.x * wv.x + xv.y * wv.y + xv.z * wv.z + xv.w * wv.w;
        }
    }
#pragma unroll
    for (int e = 0; e < NEXP; e++)
#pragma unroll
        for (int off = 16; off; off >>= 1)
            acc[e] += __shfl_xor_sync(0xffffffffu, acc[e], off);

    if (lane == 0) {
        // top-1
        int i1 = 0; float m1 = acc[0];
#pragma unroll
        for (int e = 1; e < NEXP; e++)
            if (acc[e] > m1) { m1 = acc[e]; i1 = e; }
        // top-2 (lowest index wins ties, matching top_k)
        int i2 = -1; float m2 = -INFINITY;
#pragma unroll
        for (int e = 0; e < NEXP; e++)
            if (e != i1 && acc[e] > m2) { m2 = acc[e]; i2 = e; }

        // softmax over {m1,m2} == softmax over all, renormalized to top-2
        float w1 = 1.0f / (1.0f + expf(m2 - m1));
        float w2 = 1.0f - w1;

        int p1 = atomicAdd(&g_count[i1], 1);
        g_tok[i1][p1] = t; g_w[i1][p1] = w1;
        int p2 = atomicAdd(&g_count[i2], 1);
        g_tok[i2][p2] = t; g_w[i2][p2] = w2;
    }
}

__global__ void prefix_kernel() {
    if (threadIdx.x == 0) {
        int s = 0;
#pragma unroll
        for (int e = 0; e < NEXP; e++) { g_base[e] = s; s += g_count[e]; }
    }
}

// ---------------- GEMM1: H = gelu(Xg @ W1[e]^T + b1[e]) ---------------------
// A: gathered token rows of x   [cnt, D]
// B: W1[e]  (row f, col d) row-major  -> C[m, f] = sum_d A[m,d] * W1[f,d]
__global__ void __launch_bounds__(256)
gemm1_kernel(const float* __restrict__ x,
             const float* __restrict__ W1,
             const float* __restrict__ b1) {
    const int e    = blockIdx.z;
    const int cnt  = g_count[e];
    const int row0 = blockIdx.y * TM;
    if (row0 >= cnt) return;
    const int col0 = blockIdx.x * TN;
    const int base = g_base[e];

    __shared__ __align__(16) float As[TK][TM + 4];
    __shared__ __align__(16) float Bs[TK][TN + 4];
    __shared__ int sTok[TM];

    const int tid = threadIdx.x;
    if (tid < TM) {
        int r = row0 + tid;
        sTok[tid] = g_tok[e][min(r, cnt - 1)];
    }
    __syncthreads();

    const int tx = tid & 15, ty = tid >> 4;
    const int lrow = tid >> 2;           // 0..63
    const int lk4  = (tid & 3) * 4;      // 0,4,8,12

    const size_t arow  = (size_t)sTok[lrow] * DDIM;
    const float* Bbase = W1 + ((size_t)e * DDIM + (col0 + lrow)) * DDIM;

    float c[4][4];
#pragma unroll
    for (int i = 0; i < 4; i++)
#pragma unroll
        for (int j = 0; j < 4; j++) c[i][j] = 0.f;

    for (int k0 = 0; k0 < DDIM; k0 += TK) {
        float4 av = *(const float4*)(x + arow + k0 + lk4);
        float4 bv = *(const float4*)(Bbase + k0 + lk4);
        __syncthreads();
        As[lk4 + 0][lrow] = av.x; As[lk4 + 1][lrow] = av.y;
        As[lk4 + 2][lrow] = av.z; As[lk4 + 3][lrow] = av.w;
        Bs[lk4 + 0][lrow] = bv.x; Bs[lk4 + 1][lrow] = bv.y;
        Bs[lk4 + 2][lrow] = bv.z; Bs[lk4 + 3][lrow] = bv.w;
        __syncthreads();
#pragma unroll
        for (int k = 0; k < TK; k++) {
            float4 a = *(const float4*)&As[k][ty * 4];
            float4 b = *(const float4*)&Bs[k][tx * 4];
            c[0][0] += a.x * b.x; c[0][1] += a.x * b.y; c[0][2] += a.x * b.z; c[0][3] += a.x * b.w;
            c[1][0] += a.y * b.x; c[1][1] += a.y * b.y; c[1][2] += a.y * b.z; c[1][3] += a.y * b.w;
            c[2][0] += a.z * b.x; c[2][1] += a.z * b.y; c[2][2] += a.z * b.z; c[2][3] += a.z * b.w;
            c[3][0] += a.w * b.x; c[3][1] += a.w * b.y; c[3][2] += a.w * b.z; c[3][3] += a.w * b.w;
        }
    }

#pragma unroll
    for (int i = 0; i < 4; i++) {
        int r = row0 + ty * 4 + i;
        if (r < cnt) {
            float* hrow = g_H + (size_t)(base + r) * DDIM;
#pragma unroll
            for (int j = 0; j < 4; j++) {
                int f = col0 + tx * 4 + j;
                float v = c[i][j] + b1[e * DDIM + f];
                // exact gelu: 0.5*v*(1+erf(v/sqrt(2)))
                hrow[f] = 0.5f * v * (1.0f + erff(v * 0.70710678118654752f));
            }
        }
    }
}

// ---------------- GEMM2: out[tok] += w * (H @ W2[e]^T + b2[e]) ---------------
// A: packed H rows [cnt, D];  B: W2[e] (row d, col f) -> C[m, d] = sum_f H[m,f]*W2[d,f]
__global__ void __launch_bounds__(256)
gemm2_kernel(const float* __restrict__ W2,
             const float* __restrict__ b2,
             float* __restrict__ out) {
    const int e    = blockIdx.z;
    const int cnt  = g_count[e];
    const int row0 = blockIdx.y * TM;
    if (row0 >= cnt) return;
    const int col0 = blockIdx.x * TN;
    const int base = g_base[e];

    __shared__ __align__(16) float As[TK][TM + 4];
    __shared__ __align__(16) float Bs[TK][TN + 4];

    const int tid = threadIdx.x;
    const int tx = tid & 15, ty = tid >> 4;
    const int lrow = tid >> 2;
    const int lk4  = (tid & 3) * 4;

    const int rA = min(row0 + lrow, cnt - 1);
    const float* Abase = g_H + (size_t)(base + rA) * DDIM;
    const float* Bbase = W2 + ((size_t)e * DDIM + (col0 + lrow)) * DDIM;

    float c[4][4];
#pragma unroll
    for (int i = 0; i < 4; i++)
#pragma unroll
        for (int j = 0; j < 4; j++) c[i][j] = 0.f;

    for (int k0 = 0; k0 < DDIM; k0 += TK) {
        float4 av = *(const float4*)(Abase + k0 + lk4);
        float4 bv = *(const float4*)(Bbase + k0 + lk4);
        __syncthreads();
        As[lk4 + 0][lrow] = av.x; As[lk4 + 1][lrow] = av.y;
        As[lk4 + 2][lrow] = av.z; As[lk4 + 3][lrow] = av.w;
        Bs[lk4 + 0][lrow] = bv.x; Bs[lk4 + 1][lrow] = bv.y;
        Bs[lk4 + 2][lrow] = bv.z; Bs[lk4 + 3][lrow] = bv.w;
        __syncthreads();
#pragma unroll
        for (int k = 0; k < TK; k++) {
            float4 a = *(const float4*)&As[k][ty * 4];
            float4 b = *(const float4*)&Bs[k][tx * 4];
            c[0][0] += a.x * b.x; c[0][1] += a.x * b.y; c[0][2] += a.x * b.z; c[0][3] += a.x * b.w;
            c[1][0] += a.y * b.x; c[1][1] += a.y * b.y; c[1][2] += a.y * b.z; c[1][3] += a.y * b.w;
            c[2][0] += a.z * b.x; c[2][1] += a.z * b.y; c[2][2] += a.z * b.z; c[2][3] += a.z * b.w;
            c[3][0] += a.w * b.x; c[3][1] += a.w * b.y; c[3][2] += a.w * b.z; c[3][3] += a.w * b.w;
        }
    }

#pragma unroll
    for (int i = 0; i < 4; i++) {
        int r = row0 + ty * 4 + i;
        if (r < cnt) {
            int   tok = g_tok[e][r];
            float w   = g_w[e][r];
            float* orow = out + (size_t)tok * DDIM;
#pragma unroll
            for (int j = 0; j < 4; j++) {
                int dcol = col0 + tx * 4 + j;
                float y = c[i][j] + b2[e * DDIM + dcol];
                atomicAdd(&orow[dcol], w * y);
            }
        }
    }
}

// ---------------- launch -----------------------------------------------------
extern "C" void kernel_launch(void* const* d_in, const int* in_sizes, int n_in,
                              void* d_out, int out_size) {
    const float* x  = (const float*)d_in[0];
    const float* Wr = (const float*)d_in[1];
    const float* W1 = (const float*)d_in[2];
    const float* b1 = (const float*)d_in[3];
    const float* W2 = (const float*)d_in[4];
    const float* b2 = (const float*)d_in[5];
    float* out = (float*)d_out;

    init_counts_kernel<<<1, 32>>>();
    router_kernel<<<T_TOKENS / 8, 256>>>(x, Wr);
    prefix_kernel<<<1, 32>>>();
    cudaMemsetAsync(d_out, 0, (size_t)out_size * sizeof(float), 0);

    dim3 grid(DDIM / TN, T_TOKENS / TM, NEXP);   // (16, 256, 8), early-exit on count
    gemm1_kernel<<<grid, 256>>>(x, W1, b1);
    gemm2_kernel<<<grid, 256>>>(W2, b2, out);
}